// round 15
// baseline (speedup 1.0000x reference)
#include <cuda_runtime.h>
#include <cuda_bf16.h>
#include <cstdint>

// dense_image_warp: out[b,y,x,c] = bilinear(image, (y,x) - flow[b,y,x,:])
// image: [B,H,W,C] f32, flow: [B,H,W,2] f32 (dy, dx). TFA clamping:
// floor clipped to [0, size-2], alpha clipped to [0,1].
//
// 256 threads, 1 pixel/thread. Fully warp-autonomous: each warp handles 32
// consecutive x in one row, stages 384 B in its private smem strip (3 STS,
// conflict-free), then lane 0 drains it with one cp.async.bulk (TMA path).
// No __syncthreads; no LDS/STG in the epilogue.

static constexpr int B = 8;
static constexpr int H = 1024;
static constexpr int W = 768;
static constexpr int C = 3;
static constexpr int ROW_STRIDE = W * C;   // 2304 floats, %4==0 -> rows share alignment

static constexpr int TX = 128;
static constexpr int TY = 2;
static constexpr int THREADS = 256;

__device__ __forceinline__ float sel4(float v0, float v1, float v2, float v3, int r) {
    return r == 0 ? v0 : (r == 1 ? v1 : (r == 2 ? v2 : v3));
}

__global__ __launch_bounds__(THREADS)
void warp_kernel(const float* __restrict__ image,
                 const float2* __restrict__ flow,
                 float* __restrict__ out)
{
    __shared__ alignas(16) float sbuf[8][96];   // one 384 B strip per warp

    const int tid  = threadIdx.x;
    const int wrp  = tid >> 5;             // 0..7
    const int lane = tid & 31;
    const int seg  = wrp & 3;              // 32-px x-segment within the 128-px tile
    const int ty   = wrp >> 2;             // 0..1

    const int x = blockIdx.x * TX + seg * 32 + lane;
    const int y = blockIdx.y * TY + ty;
    const int b = blockIdx.z;

    const int pix = (b * H + y) * W + x;

    float2 f = flow[pix];                  // f.x = dy, f.y = dx
    float qy = (float)y - f.x;
    float qx = (float)x - f.y;

    float y0f = fminf(fmaxf(floorf(qy), 0.0f), (float)(H - 2));
    float x0f = fminf(fmaxf(floorf(qx), 0.0f), (float)(W - 2));
    float ay  = fminf(fmaxf(qy - y0f, 0.0f), 1.0f);
    float ax  = fminf(fmaxf(qx - x0f, 0.0f), 1.0f);

    int pidx = ((b * H + (int)y0f) * W + (int)x0f) * C;
    int base = pidx & ~3;                  // 16B-aligned float index
    int r    = pidx & 3;

    const float4* imgT = (const float4*)(image + base);
    const float4* imgB = (const float4*)(image + base + ROW_STRIDE);

    // Batch loads for MLP. Worst-case extra index (r==3) lands within image.
    float4 ta = __ldg(imgT + 0);
    float4 tb = __ldg(imgT + 1);
    float4 ba = __ldg(imgB + 0);
    float4 bb = __ldg(imgB + 1);
    float  t8 = 0.0f, b8 = 0.0f;
    if (r == 3) {
        t8 = __ldg(image + base + 8);
        b8 = __ldg(image + base + ROW_STRIDE + 8);
    }

    // Vertical lerp on the 9 raw lanes (FMA pipe).
    float v0 = ta.x + ay * (ba.x - ta.x);
    float v1 = ta.y + ay * (ba.y - ta.y);
    float v2 = ta.z + ay * (ba.z - ta.z);
    float v3 = ta.w + ay * (ba.w - ta.w);
    float v4 = tb.x + ay * (bb.x - tb.x);
    float v5 = tb.y + ay * (bb.y - tb.y);
    float v6 = tb.z + ay * (bb.z - tb.z);
    float v7 = tb.w + ay * (bb.w - tb.w);
    float v8 = t8   + ay * (b8   - t8);

    // Horizontal lerp: u[j] pairs lane j with lane j+3.
    float u0 = v0 + ax * (v3 - v0);
    float u1 = v1 + ax * (v4 - v1);
    float u2 = v2 + ax * (v5 - v2);
    float u3 = v3 + ax * (v6 - v3);
    float u4 = v4 + ax * (v7 - v4);
    float u5 = v5 + ax * (v8 - v5);

    // Extract the 3 output channels (lanes r, r+1, r+2 of u) into the strip.
    float* s = &sbuf[wrp][lane * 3];
    s[0] = sel4(u0, u1, u2, u3, r);
    s[1] = sel4(u1, u2, u3, u4, r);
    s[2] = sel4(u2, u3, u4, u5, r);

    __syncwarp();

    // Warp-autonomous drain: one 384 B bulk copy per warp, no block barrier.
    if (lane == 0) {
        asm volatile("fence.proxy.async.shared::cta;" ::: "memory");
        uint32_t saddr;
        asm("{ .reg .u64 t; cvta.to.shared.u64 t, %1; cvt.u32.u64 %0, t; }"
            : "=r"(saddr) : "l"(&sbuf[wrp][0]));
        float* gdst = out + ((size_t)(b * H + y) * W + blockIdx.x * TX + seg * 32) * C;
        asm volatile(
            "cp.async.bulk.global.shared::cta.bulk_group [%0], [%1], %2;"
            :: "l"(gdst), "r"(saddr), "n"(96 * 4)
            : "memory");
        asm volatile("cp.async.bulk.commit_group;" ::: "memory");
        asm volatile("cp.async.bulk.wait_group 0;" ::: "memory");
    }
}

extern "C" void kernel_launch(void* const* d_in, const int* in_sizes, int n_in,
                              void* d_out, int out_size)
{
    const float*  image = (const float*)d_in[0];
    const float2* flow  = (const float2*)d_in[1];
    float*        outp  = (float*)d_out;

    dim3 grid(W / TX, H / TY, B);          // (6, 512, 8) exact
    warp_kernel<<<grid, THREADS>>>(image, flow, outp);
}

// round 16
// speedup vs baseline: 1.1110x; 1.1110x over previous
#include <cuda_runtime.h>
#include <cuda_bf16.h>
#include <cstdint>

// dense_image_warp: out[b,y,x,c] = bilinear(image, (y,x) - flow[b,y,x,:])
// image: [B,H,W,C] f32, flow: [B,H,W,2] f32 (dy, dx). TFA clamping:
// floor clipped to [0, size-2], alpha clipped to [0,1].
//
// 128 threads/block, 1 pixel/thread, one 128-px output row segment per block.
// Vertical-first bilinear on raw vector lanes. Epilogue: STS staging, one
// __syncthreads over just 4 warps, then a single 1536 B cp.async.bulk drain
// (one fence + one copy per block -- amortized, unlike the per-warp R15
// variant which regressed).

static constexpr int B = 8;
static constexpr int H = 1024;
static constexpr int W = 768;
static constexpr int C = 3;
static constexpr int ROW_STRIDE = W * C;   // 2304 floats, %4==0 -> rows share alignment

static constexpr int TX = 128;
static constexpr int THREADS = 128;
static constexpr int SEG_FLOATS = TX * C;  // 384 floats = 1536 B

__device__ __forceinline__ float sel4(float v0, float v1, float v2, float v3, int r) {
    return r == 0 ? v0 : (r == 1 ? v1 : (r == 2 ? v2 : v3));
}

__global__ __launch_bounds__(THREADS)
void warp_kernel(const float* __restrict__ image,
                 const float2* __restrict__ flow,
                 float* __restrict__ out)
{
    __shared__ alignas(16) float sbuf[SEG_FLOATS];   // 1536 B

    const int tid = threadIdx.x;

    const int x = blockIdx.x * TX + tid;
    const int y = blockIdx.y;
    const int b = blockIdx.z;

    const int pix = (b * H + y) * W + x;

    float2 f = flow[pix];                  // f.x = dy, f.y = dx
    float qy = (float)y - f.x;
    float qx = (float)x - f.y;

    float y0f = fminf(fmaxf(floorf(qy), 0.0f), (float)(H - 2));
    float x0f = fminf(fmaxf(floorf(qx), 0.0f), (float)(W - 2));
    float ay  = fminf(fmaxf(qy - y0f, 0.0f), 1.0f);
    float ax  = fminf(fmaxf(qx - x0f, 0.0f), 1.0f);

    int pidx = ((b * H + (int)y0f) * W + (int)x0f) * C;
    int base = pidx & ~3;                  // 16B-aligned float index
    int r    = pidx & 3;

    const float4* imgT = (const float4*)(image + base);
    const float4* imgB = (const float4*)(image + base + ROW_STRIDE);

    // Batch loads for MLP. Worst-case extra index (r==3) lands within image.
    float4 ta = __ldg(imgT + 0);
    float4 tb = __ldg(imgT + 1);
    float4 ba = __ldg(imgB + 0);
    float4 bb = __ldg(imgB + 1);
    float  t8 = 0.0f, b8 = 0.0f;
    if (r == 3) {
        t8 = __ldg(image + base + 8);
        b8 = __ldg(image + base + ROW_STRIDE + 8);
    }

    // Vertical lerp on the 9 raw lanes (FMA pipe).
    float v0 = ta.x + ay * (ba.x - ta.x);
    float v1 = ta.y + ay * (ba.y - ta.y);
    float v2 = ta.z + ay * (ba.z - ta.z);
    float v3 = ta.w + ay * (ba.w - ta.w);
    float v4 = tb.x + ay * (bb.x - tb.x);
    float v5 = tb.y + ay * (bb.y - tb.y);
    float v6 = tb.z + ay * (bb.z - tb.z);
    float v7 = tb.w + ay * (bb.w - tb.w);
    float v8 = t8   + ay * (b8   - t8);

    // Horizontal lerp: u[j] pairs lane j with lane j+3.
    float u0 = v0 + ax * (v3 - v0);
    float u1 = v1 + ax * (v4 - v1);
    float u2 = v2 + ax * (v5 - v2);
    float u3 = v3 + ax * (v6 - v3);
    float u4 = v4 + ax * (v7 - v4);
    float u5 = v5 + ax * (v8 - v5);

    // Extract the 3 output channels (lanes r, r+1, r+2 of u).
    float* s = &sbuf[tid * 3];
    s[0] = sel4(u0, u1, u2, u3, r);
    s[1] = sel4(u1, u2, u3, u4, r);
    s[2] = sel4(u2, u3, u4, u5, r);

    __syncthreads();                       // 4 warps only

    // Single 1536 B bulk drain per block (one fence, one copy, one wait).
    if (tid == 0) {
        asm volatile("fence.proxy.async.shared::cta;" ::: "memory");
        uint32_t saddr;
        asm("{ .reg .u64 t; cvta.to.shared.u64 t, %1; cvt.u32.u64 %0, t; }"
            : "=r"(saddr) : "l"(&sbuf[0]));
        float* gdst = out + ((size_t)(b * H + y) * W + blockIdx.x * TX) * C;
        asm volatile(
            "cp.async.bulk.global.shared::cta.bulk_group [%0], [%1], %2;"
            :: "l"(gdst), "r"(saddr), "n"(SEG_FLOATS * 4)
            : "memory");
        asm volatile("cp.async.bulk.commit_group;" ::: "memory");
        asm volatile("cp.async.bulk.wait_group 0;" ::: "memory");
    }
}

extern "C" void kernel_launch(void* const* d_in, const int* in_sizes, int n_in,
                              void* d_out, int out_size)
{
    const float*  image = (const float*)d_in[0];
    const float2* flow  = (const float2*)d_in[1];
    float*        outp  = (float*)d_out;

    dim3 grid(W / TX, H, B);               // (6, 1024, 8) exact
    warp_kernel<<<grid, THREADS>>>(image, flow, outp);
}